// round 11
// baseline (speedup 1.0000x reference)
#include <cuda_runtime.h>

// PercolationQ: per-patch occupancy fraction -> threshold -> mean over patches.
// Pure HBM-bound streaming reduction over three 50 MB fp32 tensors.
//
//   x4 : [3,64,4096,4,4]   patch = 16 floats  (4 lanes)
//   x8 : [3,64,1024,8,8]   patch = 64 floats  (16 lanes)
//   x16: [3,64, 256,16,16] patch = 256 floats (2 warp-iterations)
// Output: [q4(3,64), q8(3,64), q16(3,64)] = 576 floats.
//
// R10: mode-W (1 CTA/SM, 148 x 1024 -- validated in R9) + DOUBLE-BUFFERED
// loads. Each warp owns exactly ONE 32 KB segment (4608 segments; balanced
// single pass). Two 8-deep float4 buffers, loop unrolled by 2: batch i+1's
// eight LDG.128s issue before batch i's reduction consumes its registers,
// keeping >=8 coalesced loads per warp in flight continuously (fixes the
// load-silent reduction gaps that left DRAM 26% idle in R9). Regs ~90 are
// free at 1 CTA x 1024 threads (256 regs/thread RF headroom).
// Integer per-warp atomicAdd (order-independent => exact), ticket finalize.

#define PERC_THR 0.59275f
#define NBLK 148
#define NTHR 1024
#define NSEG 4608              // 32 KB segments: 3 * 50.3 MB / 32 KB

__device__ int g_cnt[576];              // per-row patch counts (int -> exact)
__device__ unsigned int g_ticket = 0;   // self-resetting -> deterministic replays

__device__ __forceinline__ float red4(float4 a) {
    return (a.x + a.y) + (a.z + a.w);
}

// Reduce one batch of 8 warp-loads (512 B each) to a local patch count.
__device__ __forceinline__ int reduce_batch(const float4 v[8], int tcase, int lane) {
    float a[8];
#pragma unroll
    for (int j = 0; j < 8; j++) a[j] = red4(v[j]);

    int cnt = 0;
    if (tcase == 0) {
        // x4: patch = 4 lanes
#pragma unroll
        for (int j = 0; j < 8; j++) {
            a[j] += __shfl_xor_sync(0xffffffffu, a[j], 1);
            a[j] += __shfl_xor_sync(0xffffffffu, a[j], 2);
        }
        if ((lane & 3) == 0) {
#pragma unroll
            for (int j = 0; j < 8; j++)
                cnt += (a[j] * 0.0625f >= PERC_THR) ? 1 : 0;
        }
    } else if (tcase == 1) {
        // x8: patch = 16 lanes
#pragma unroll
        for (int j = 0; j < 8; j++) {
#pragma unroll
            for (int m = 1; m <= 8; m <<= 1)
                a[j] += __shfl_xor_sync(0xffffffffu, a[j], m);
        }
        if ((lane & 15) == 0) {
#pragma unroll
            for (int j = 0; j < 8; j++)
                cnt += (a[j] * 0.015625f >= PERC_THR) ? 1 : 0;
        }
    } else {
        // x16: patch = 2 consecutive warp-iterations -> 4 patches per batch
        float b[4];
#pragma unroll
        for (int j = 0; j < 4; j++) b[j] = a[2 * j] + a[2 * j + 1];
#pragma unroll
        for (int j = 0; j < 4; j++) {
#pragma unroll
            for (int m = 1; m <= 16; m <<= 1)
                b[j] += __shfl_xor_sync(0xffffffffu, b[j], m);
        }
        if (lane == 0) {
#pragma unroll
            for (int j = 0; j < 4; j++)
                cnt += (b[j] * 0.00390625f >= PERC_THR) ? 1 : 0;
        }
    }
    return cnt;
}

__global__ void __launch_bounds__(NTHR, 1)
perc_kernel(const float* __restrict__ x4,
            const float* __restrict__ x8,
            const float* __restrict__ x16,
            float* __restrict__ out) {
    __shared__ bool sh_last;

    const int tid  = threadIdx.x;
    const int lane = tid & 31;
    const int seg  = blockIdx.x * 32 + (tid >> 5);   // one 32 KB segment per warp

    if (seg < NSEG) {
        // Segment -> tensor + base. 32 KB = 2048 float4; row = 256 KB = 8 segs;
        // global row id = seg >> 3 (tensor boundaries align: 1536>>3 = 192).
        const float4* p;
        int tcase;
        if (seg < 1536)      { p = (const float4*)x4  + (size_t)seg * 2048;          tcase = 0; }
        else if (seg < 3072) { p = (const float4*)x8  + (size_t)(seg - 1536) * 2048; tcase = 1; }
        else                 { p = (const float4*)x16 + (size_t)(seg - 3072) * 2048; tcase = 2; }

        // 8 batches of 8 warp-loads (batch = 256 float4 = 2 KB), double-buffered.
        float4 va[8], vb[8];
        int cnt = 0;

#pragma unroll
        for (int j = 0; j < 8; j++) va[j] = p[j * 32 + lane];          // batch 0

#pragma unroll 1
        for (int i = 0; i < 8; i += 2) {
            if (i + 1 < 8) {
#pragma unroll
                for (int j = 0; j < 8; j++)                            // batch i+1
                    vb[j] = p[(i + 1) * 256 + j * 32 + lane];
            }
            cnt += reduce_batch(va, tcase, lane);                      // batch i
            if (i + 2 < 8) {
#pragma unroll
                for (int j = 0; j < 8; j++)                            // batch i+2
                    va[j] = p[(i + 2) * 256 + j * 32 + lane];
            }
            if (i + 1 < 8)
                cnt += reduce_batch(vb, tcase, lane);                  // batch i+1
        }

        // Warp total -> one integer atomic per segment (order-independent, exact)
        cnt = __reduce_add_sync(0xffffffffu, cnt);
        if (lane == 0) atomicAdd(&g_cnt[seg >> 3], cnt);
    }

    // ---- last-block finalize (threadfence-reduction ticket pattern) ----
    __syncthreads();
    if (tid == 0) {
        __threadfence();                       // publish this block's atomics
        unsigned int t = atomicAdd(&g_ticket, 1);
        sh_last = (t == NBLK - 1);
    }
    __syncthreads();
    if (sh_last) {
        for (int t = tid; t < 576; t += NTHR) {
            int c = g_cnt[t];
            const float invP = (t < 192) ? (1.0f / 4096.0f)
                             : (t < 384) ? (1.0f / 1024.0f)
                                         : (1.0f / 256.0f);
            out[t] = (float)c * invP;
            g_cnt[t] = 0;                      // reset for next graph replay
        }
        if (tid == 0) g_ticket = 0;
    }
}

extern "C" void kernel_launch(void* const* d_in, const int* in_sizes, int n_in,
                              void* d_out, int out_size) {
    const float* x4  = (const float*)d_in[0];
    const float* x8  = (const float*)d_in[1];
    const float* x16 = (const float*)d_in[2];
    float* out = (float*)d_out;

    perc_kernel<<<NBLK, NTHR>>>(x4, x8, x16, out);
}

// round 12
// speedup vs baseline: 1.1231x; 1.1231x over previous
#include <cuda_runtime.h>

// PercolationQ: per-patch occupancy fraction -> threshold -> mean over patches.
// Pure HBM-bound streaming reduction over three 50 MB fp32 tensors.
//
//   x4 : [3,64,4096,4,4]   patch = 16 floats  (4 lanes)
//   x8 : [3,64,1024,8,8]   patch = 64 floats  (16 lanes)
//   x16: [3,64, 256,16,16] patch = 256 floats (2 warp-iterations)
// Output: [q4(3,64), q8(3,64), q16(3,64)] = 576 floats.
//
// R11: mode-W (1 CTA/SM, 148 x 1024 -- R9-validated) + double buffering that
// FITS the 64-reg/thread cap of 1024-thread blocks (R10 spilled: 2x8 float4
// buffers = 128 regs -> local-memory spill, DRAM 53%). Here: 2 x 4-deep
// float4 buffers = 32 data regs, ~56 total. One 32 KB segment per warp
// (4608 segments, balanced single pass). Pipeline: prefetch batch i+1's four
// coalesced LDG.128 before reducing batch i -> each warp holds >=4 loads in
// flight continuously. Integer per-warp atomicAdd (order-independent =>
// exact), last-block ticket finalize, self-resetting for graph replays.

#define PERC_THR 0.59275f
#define NBLK 148
#define NTHR 1024
#define NSEG 4608              // 32 KB segments: 3 * 50.3 MB / 32 KB
#define NBATCH 16              // 16 batches x 4 warp-loads x 512 B = 32 KB

__device__ int g_cnt[576];              // per-row patch counts (int -> exact)
__device__ unsigned int g_ticket = 0;   // self-resetting -> deterministic replays

__device__ __forceinline__ float red4(float4 a) {
    return (a.x + a.y) + (a.z + a.w);
}

// Reduce one batch of 4 warp-loads (512 B each) to a local patch count.
__device__ __forceinline__ int reduce_batch(const float4 v[4], int tcase, int lane) {
    float a0 = red4(v[0]), a1 = red4(v[1]), a2 = red4(v[2]), a3 = red4(v[3]);
    int cnt = 0;
    if (tcase == 0) {
        // x4: patch = 4 lanes; 8 patches per warp-load
        a0 += __shfl_xor_sync(0xffffffffu, a0, 1);
        a1 += __shfl_xor_sync(0xffffffffu, a1, 1);
        a2 += __shfl_xor_sync(0xffffffffu, a2, 1);
        a3 += __shfl_xor_sync(0xffffffffu, a3, 1);
        a0 += __shfl_xor_sync(0xffffffffu, a0, 2);
        a1 += __shfl_xor_sync(0xffffffffu, a1, 2);
        a2 += __shfl_xor_sync(0xffffffffu, a2, 2);
        a3 += __shfl_xor_sync(0xffffffffu, a3, 2);
        if ((lane & 3) == 0) {
            cnt += (a0 * 0.0625f >= PERC_THR) ? 1 : 0;
            cnt += (a1 * 0.0625f >= PERC_THR) ? 1 : 0;
            cnt += (a2 * 0.0625f >= PERC_THR) ? 1 : 0;
            cnt += (a3 * 0.0625f >= PERC_THR) ? 1 : 0;
        }
    } else if (tcase == 1) {
        // x8: patch = 16 lanes
#pragma unroll
        for (int m = 1; m <= 8; m <<= 1) {
            a0 += __shfl_xor_sync(0xffffffffu, a0, m);
            a1 += __shfl_xor_sync(0xffffffffu, a1, m);
            a2 += __shfl_xor_sync(0xffffffffu, a2, m);
            a3 += __shfl_xor_sync(0xffffffffu, a3, m);
        }
        if ((lane & 15) == 0) {
            cnt += (a0 * 0.015625f >= PERC_THR) ? 1 : 0;
            cnt += (a1 * 0.015625f >= PERC_THR) ? 1 : 0;
            cnt += (a2 * 0.015625f >= PERC_THR) ? 1 : 0;
            cnt += (a3 * 0.015625f >= PERC_THR) ? 1 : 0;
        }
    } else {
        // x16: patch = 2 consecutive warp-loads -> 2 patches per batch
        float b0 = a0 + a1;
        float b1 = a2 + a3;
#pragma unroll
        for (int m = 1; m <= 16; m <<= 1) {
            b0 += __shfl_xor_sync(0xffffffffu, b0, m);
            b1 += __shfl_xor_sync(0xffffffffu, b1, m);
        }
        if (lane == 0) {
            cnt += (b0 * 0.00390625f >= PERC_THR) ? 1 : 0;
            cnt += (b1 * 0.00390625f >= PERC_THR) ? 1 : 0;
        }
    }
    return cnt;
}

__global__ void __launch_bounds__(NTHR, 1)
perc_kernel(const float* __restrict__ x4,
            const float* __restrict__ x8,
            const float* __restrict__ x16,
            float* __restrict__ out) {
    __shared__ bool sh_last;

    const int tid  = threadIdx.x;
    const int lane = tid & 31;
    const int seg  = blockIdx.x * 32 + (tid >> 5);   // one 32 KB segment per warp

    if (seg < NSEG) {
        // Segment -> tensor + base. 32 KB = 2048 float4; row = 256 KB = 8 segs;
        // global row id = seg >> 3 (tensor boundaries align: 1536>>3 = 192).
        const float4* p;
        int tcase;
        if (seg < 1536)      { p = (const float4*)x4  + (size_t)seg * 2048;          tcase = 0; }
        else if (seg < 3072) { p = (const float4*)x8  + (size_t)(seg - 1536) * 2048; tcase = 1; }
        else                 { p = (const float4*)x16 + (size_t)(seg - 3072) * 2048; tcase = 2; }
        p += lane;

        // 16 batches of 4 warp-loads (batch = 128 float4 = 512 B/lane-row x 4),
        // double-buffered at depth 4 (2 x 4 float4 = 32 data regs, no spill).
        float4 va[4], vb[4];
        int cnt = 0;

#pragma unroll
        for (int j = 0; j < 4; j++) va[j] = p[j * 32];                 // batch 0

#pragma unroll 1
        for (int i = 0; i < NBATCH; i += 2) {
            if (i + 1 < NBATCH) {
#pragma unroll
                for (int j = 0; j < 4; j++)                            // batch i+1
                    vb[j] = p[(i + 1) * 128 + j * 32];
            }
            cnt += reduce_batch(va, tcase, lane);                      // batch i
            if (i + 2 < NBATCH) {
#pragma unroll
                for (int j = 0; j < 4; j++)                            // batch i+2
                    va[j] = p[(i + 2) * 128 + j * 32];
            }
            if (i + 1 < NBATCH)
                cnt += reduce_batch(vb, tcase, lane);                  // batch i+1
        }

        // Warp total -> one integer atomic per segment (order-independent, exact)
        cnt = __reduce_add_sync(0xffffffffu, cnt);
        if (lane == 0) atomicAdd(&g_cnt[seg >> 3], cnt);
    }

    // ---- last-block finalize (threadfence-reduction ticket pattern) ----
    __syncthreads();
    if (tid == 0) {
        __threadfence();                       // publish this block's atomics
        unsigned int t = atomicAdd(&g_ticket, 1);
        sh_last = (t == NBLK - 1);
    }
    __syncthreads();
    if (sh_last) {
        for (int t = tid; t < 576; t += NTHR) {
            int c = g_cnt[t];
            const float invP = (t < 192) ? (1.0f / 4096.0f)
                             : (t < 384) ? (1.0f / 1024.0f)
                                         : (1.0f / 256.0f);
            out[t] = (float)c * invP;
            g_cnt[t] = 0;                      // reset for next graph replay
        }
        if (tid == 0) g_ticket = 0;
    }
}

extern "C" void kernel_launch(void* const* d_in, const int* in_sizes, int n_in,
                              void* d_out, int out_size) {
    const float* x4  = (const float*)d_in[0];
    const float* x8  = (const float*)d_in[1];
    const float* x16 = (const float*)d_in[2];
    float* out = (float*)d_out;

    perc_kernel<<<NBLK, NTHR>>>(x4, x8, x16, out);
}